// round 12
// baseline (speedup 1.0000x reference)
#include <cuda_runtime.h>
#include <cuda_bf16.h>
#include <cstdint>
#include <math.h>

// Problem constants
#define BB   4
#define SS   1024
#define DD   1024
#define HH   16
#define DKK  64
#define DFFN 4096
#define MM   (BB*SS)        // 4096 token rows
#define BH   (BB*HH)        // 64

// ---------------------------------------------------------------------------
// Scratch
// ---------------------------------------------------------------------------
__device__ float g_q[MM*DD];
__device__ float g_k[MM*DD];
__device__ float g_v[MM*DD];      // V TRANSPOSED: [(b*1024+col)*1024 + t]
__device__ float g_k2[MM*DD];     // CA k
__device__ float g_v2[MM*DD];     // CA v (transposed)
__device__ float g_attn[MM*DD];
__device__ float g_tmp[MM*DD];
__device__ float g_x1[MM*DD];
__device__ float g_x2[MM*DD];
__device__ float g_hidden[(long long)MM*DFFN];    // 67MB

// ---------------------------------------------------------------------------
// helpers
// ---------------------------------------------------------------------------
__device__ __forceinline__ unsigned int f2tf32(float f) {
    unsigned int r;
    asm("cvt.rna.tf32.f32 %0, %1;" : "=r"(r) : "f"(f));
    return r;
}

__device__ __forceinline__ void mma_tf32(float (&c)[4],
                                         const unsigned int (&a)[4],
                                         const unsigned int (&b)[2]) {
    asm volatile(
        "mma.sync.aligned.m16n8k8.row.col.f32.tf32.tf32.f32 "
        "{%0,%1,%2,%3}, {%4,%5,%6,%7}, {%8,%9}, {%0,%1,%2,%3};"
        : "+f"(c[0]), "+f"(c[1]), "+f"(c[2]), "+f"(c[3])
        : "r"(a[0]), "r"(a[1]), "r"(a[2]), "r"(a[3]),
          "r"(b[0]), "r"(b[1]));
}

__device__ __forceinline__ void cp16(unsigned int saddr, const float* g) {
    asm volatile("cp.async.cg.shared.global [%0], [%1], 16;\n" :: "r"(saddr), "l"(g));
}
__device__ __forceinline__ void cp_commit() {
    asm volatile("cp.async.commit_group;\n" ::);
}
__device__ __forceinline__ void cp_wait1() {
    asm volatile("cp.async.wait_group 1;\n" ::);
}
__device__ __forceinline__ void cp_wait0() {
    asm volatile("cp.async.wait_group 0;\n" ::);
}

// Per-z operand table for the merged projection launch (passed by value).
struct P5 {
    const float* A[5];
    const float* B[5];
    const float* bias[5];
    float*       C[5];
    int          trans[5];
};

// ---------------------------------------------------------------------------
// Core 128x128 tf32 GEMM body (TN), 3-stage cp.async pipeline.
// wait_group 1 (= Stages-2) before compute of tile `it`: committed groups are
// G0..G_{it+1}; wait1 forces G_it complete, leaves G_{it+1} in flight (issued
// a full iteration earlier -> ~2 compute phases of latency cover).
// Stage indices are compile-time literals (macro-expanded).
// ---------------------------------------------------------------------------
template<bool RELU, bool ROUND_OUT>
__device__ __forceinline__ void gemm_body_128(
    const float* __restrict__ A, const float* __restrict__ B,
    const float* __restrict__ bias, float* __restrict__ C,
    int lda, int ldb, int ldc, int K, int trans_out, float* smem)
{
    constexpr int BM = 128, BN = 128, WM = 64, WN = 32;
    constexpr int MT = WM / 16;       // 4
    constexpr int NT = WN / 8;        // 4
    constexpr int NWN = BN / WN;      // 4

    float* AsBase = smem;                    // 3 stages of BM*36
    float* BsBase = smem + 3 * BM * 36;      // 3 stages of BN*36

    const int row0 = blockIdx.y * BM;
    const int col0 = blockIdx.x * BN;
    const int t    = threadIdx.x;
    const int w    = t >> 5;
    const int lane = t & 31;
    const int wm   = w / NWN;
    const int wn   = w % NWN;
    const int gr   = lane >> 2;
    const int gc   = lane & 3;

    const int m0 = t >> 3;
    const int kq = t & 7;

    const float* gA = A + (long long)(row0 + m0) * lda + kq * 4;
    const float* gB = B + (long long)(col0 + m0) * ldb + kq * 4;

    unsigned int aBase = (unsigned int)__cvta_generic_to_shared(AsBase);
    unsigned int bBase = (unsigned int)__cvta_generic_to_shared(BsBase);
    constexpr unsigned int stageA = BM * 36 * 4;
    constexpr unsigned int stageB = BN * 36 * 4;

    float acc[MT][NT][4];
    #pragma unroll
    for (int i = 0; i < MT; i++)
        #pragma unroll
        for (int j = 0; j < NT; j++)
            #pragma unroll
            for (int r = 0; r < 4; r++) acc[i][j][r] = 0.f;

    const int nk = K >> 5;   // 32 or 128: both == 2 (mod 3)

    // prologue: tile 0 -> stage 0 (group G0), tile 1 -> stage 1 (group G1)
    #pragma unroll
    for (int i = 0; i < BM / 32; i++)
        cp16(aBase + ((m0 + 32 * i) * 36 + kq * 4) * 4, gA + (long long)(32 * i) * lda);
    #pragma unroll
    for (int i = 0; i < BN / 32; i++)
        cp16(bBase + ((m0 + 32 * i) * 36 + kq * 4) * 4, gB + (long long)(32 * i) * ldb);
    cp_commit();
    #pragma unroll
    for (int i = 0; i < BM / 32; i++)
        cp16(aBase + stageA + ((m0 + 32 * i) * 36 + kq * 4) * 4, gA + 32 + (long long)(32 * i) * lda);
    #pragma unroll
    for (int i = 0; i < BN / 32; i++)
        cp16(bBase + stageB + ((m0 + 32 * i) * 36 + kq * 4) * 4, gB + 32 + (long long)(32 * i) * ldb);
    cp_commit();

#define PREFETCH_TILE(W)                                                          \
    {                                                                             \
        const float* gA2 = gA + (it + 2) * 32;                                    \
        const float* gB2 = gB + (it + 2) * 32;                                    \
        _Pragma("unroll")                                                         \
        for (int i = 0; i < BM / 32; i++)                                         \
            cp16(aBase + (W) * stageA + ((m0 + 32 * i) * 36 + kq * 4) * 4,        \
                 gA2 + (long long)(32 * i) * lda);                                \
        _Pragma("unroll")                                                         \
        for (int i = 0; i < BN / 32; i++)                                         \
            cp16(bBase + (W) * stageB + ((m0 + 32 * i) * 36 + kq * 4) * 4,        \
                 gB2 + (long long)(32 * i) * ldb);                                \
    }

#define COMPUTE_TILE(S)                                                           \
    {                                                                             \
        const float* Acur = AsBase + (S) * (BM * 36);                             \
        const float* Bcur = BsBase + (S) * (BN * 36);                             \
        _Pragma("unroll")                                                         \
        for (int ks = 0; ks < 32; ks += 8) {                                      \
            unsigned int af[MT][4];                                               \
            unsigned int bf[NT][2];                                               \
            _Pragma("unroll")                                                     \
            for (int mt = 0; mt < MT; mt++) {                                     \
                int r = wm * WM + mt * 16 + gr;                                   \
                af[mt][0] = f2tf32(Acur[(r    ) * 36 + ks + gc]);                 \
                af[mt][1] = f2tf32(Acur[(r + 8) * 36 + ks + gc]);                 \
                af[mt][2] = f2tf32(Acur[(r    ) * 36 + ks + gc + 4]);             \
                af[mt][3] = f2tf32(Acur[(r + 8) * 36 + ks + gc + 4]);             \
            }                                                                     \
            _Pragma("unroll")                                                     \
            for (int nt = 0; nt < NT; nt++) {                                     \
                int n = wn * WN + nt * 8 + gr;                                    \
                bf[nt][0] = f2tf32(Bcur[n * 36 + ks + gc]);                       \
                bf[nt][1] = f2tf32(Bcur[n * 36 + ks + gc + 4]);                   \
            }                                                                     \
            _Pragma("unroll")                                                     \
            for (int mt = 0; mt < MT; mt++)                                       \
                _Pragma("unroll")                                                 \
                for (int nt = 0; nt < NT; nt++)                                   \
                    mma_tf32(acc[mt][nt], af[mt], bf[nt]);                        \
        }                                                                         \
    }

#define GEMM_STEP(S, W)                                                           \
    {                                                                             \
        cp_wait1();                                                               \
        __syncthreads();                                                          \
        if (it + 2 < nk) PREFETCH_TILE(W);                                        \
        cp_commit();                                                              \
        COMPUTE_TILE(S);                                                          \
        it++;                                                                     \
    }

    int it = 0;
    while (it + 3 <= nk) {
        GEMM_STEP(0, 2)
        GEMM_STEP(1, 0)
        GEMM_STEP(2, 1)
    }
    // nk % 3 == 2 for K=1024 and K=4096: remainder tiles at stages 0, 1
    GEMM_STEP(0, 2)
    GEMM_STEP(1, 0)

#undef GEMM_STEP
#undef COMPUTE_TILE
#undef PREFETCH_TILE

    // ---- Epilogue ----
    #pragma unroll
    for (int mt = 0; mt < MT; mt++) {
        #pragma unroll
        for (int nt = 0; nt < NT; nt++) {
            int row = row0 + wm * WM + mt * 16 + gr;
            int col = col0 + wn * WN + nt * 8 + gc * 2;
            float b0 = 0.f, b1 = 0.f;
            if (bias) { b0 = bias[col]; b1 = bias[col + 1]; }
            float v0 = acc[mt][nt][0] + b0;
            float v1 = acc[mt][nt][1] + b1;
            float v2 = acc[mt][nt][2] + b0;
            float v3 = acc[mt][nt][3] + b1;
            if (RELU) {
                v0 = fmaxf(v0, 0.f); v1 = fmaxf(v1, 0.f);
                v2 = fmaxf(v2, 0.f); v3 = fmaxf(v3, 0.f);
            }
            if (ROUND_OUT) {
                v0 = __uint_as_float(f2tf32(v0));
                v1 = __uint_as_float(f2tf32(v1));
                v2 = __uint_as_float(f2tf32(v2));
                v3 = __uint_as_float(f2tf32(v3));
            }
            if (trans_out) {
                int rb = row >> 10;
                int tt = row & 1023;
                long long a0 = ((long long)(rb * 1024 + col) << 10) + tt;
                C[a0]            = v0;
                C[a0 + 1024]     = v1;
                C[a0 + 8]        = v2;
                C[a0 + 1024 + 8] = v3;
            } else {
                *(float2*)(C + (long long)row * ldc + col)       = make_float2(v0, v1);
                *(float2*)(C + (long long)(row + 8) * ldc + col) = make_float2(v2, v3);
            }
        }
    }
}

// Generic single-GEMM wrapper (out-projections, FFN, CA-q).
template<bool RELU, bool ROUND_OUT, bool TRANS_OUT>
__global__ void __launch_bounds__(256, 2) gemm_tc(
    const float* __restrict__ A, int lda,
    const float* __restrict__ B, int ldb,
    const float* __restrict__ bias,
    float* __restrict__ C, int ldc, int K)
{
    extern __shared__ float smem[];
    gemm_body_128<RELU, ROUND_OUT>(A, B, bias, C, lda, ldb, ldc, K,
                                   TRANS_OUT ? 1 : 0, smem);
}

// Merged independent projections: z selects operands (SAq,SAk,SAv,CAk,CAv).
__global__ void __launch_bounds__(256, 2) gemm_qkv5(P5 p, int K)
{
    extern __shared__ float smem[];
    const int z = blockIdx.z;
    gemm_body_128<false, true>(p.A[z], p.B[z], p.bias[z], p.C[z],
                               DD, DD, DD, K, p.trans[z], smem);
}

// ---------------------------------------------------------------------------
// Flash attention with cp.async double-buffered K/V tiles  [R9 proven].
// ---------------------------------------------------------------------------
#define FQT 128
#define FKT 64
#define FSB 68

template<bool CAUSAL>
__global__ void __launch_bounds__(256, 2) flash_attn(
    const float* __restrict__ Q, const float* __restrict__ K,
    const float* __restrict__ VT, float* __restrict__ O)
{
    extern __shared__ float sm[];
    float* Kb = sm;                       // [2][FKT][FSB]
    float* Vb = sm + 2 * FKT * FSB;       // [2][64][FSB]
    float* Pb = sm + 4 * FKT * FSB;       // [FQT][FSB]

    const int qi = CAUSAL ? ((int)gridDim.x - 1 - (int)blockIdx.x) : (int)blockIdx.x;
    const int bh = blockIdx.y;
    const int b  = bh >> 4;
    const int h  = bh & 15;

    const int t    = threadIdx.x;
    const int w    = t >> 5;
    const int lane = t & 31;
    const int gr   = lane >> 2;
    const int gc   = lane & 3;
    const int wrow = w * 16;

    const long long rowbase = (long long)b * SS;
    const float* Qp = Q + (rowbase + qi * FQT) * DD + h * 64;
    const float* Kp = K + rowbase * DD + h * 64;
    const float* Vp = VT + (((long long)(b * 1024 + h * 64)) << 10);
    float* Op = O + (rowbase + qi * FQT) * DD + h * 64;

    unsigned int kbase = (unsigned int)__cvta_generic_to_shared(Kb);
    unsigned int vbase = (unsigned int)__cvta_generic_to_shared(Vb);
    constexpr unsigned int stageK = FKT * FSB * 4;

    #pragma unroll
    for (int i = 0; i < 8; i++) {
        int l  = t + i * 256;
        int m  = l >> 4;
        int q4 = l & 15;
        float4 v = *(const float4*)(Qp + (long long)m * DD + q4 * 4);
        *(float4*)&Pb[m * FSB + q4 * 4] = v;
    }
    __syncthreads();

    unsigned int qf[8][4];
    #pragma unroll
    for (int ks = 0; ks < 8; ks++) {
        qf[ks][0] = __float_as_uint(Pb[(wrow + gr    ) * FSB + ks * 8 + gc]);
        qf[ks][1] = __float_as_uint(Pb[(wrow + gr + 8) * FSB + ks * 8 + gc]);
        qf[ks][2] = __float_as_uint(Pb[(wrow + gr    ) * FSB + ks * 8 + gc + 4]);
        qf[ks][3] = __float_as_uint(Pb[(wrow + gr + 8) * FSB + ks * 8 + gc + 4]);
    }
    __syncthreads();

    float o[8][4];
    #pragma unroll
    for (int i = 0; i < 8; i++)
        #pragma unroll
        for (int r = 0; r < 4; r++) o[i][r] = 0.f;
    float m0 = -1e30f, m1 = -1e30f, l0 = 0.f, l1 = 0.f;

    const int rg0 = qi * FQT + wrow + gr;
    const int rg1 = rg0 + 8;
    const int jmax = CAUSAL ? (2 * qi + 1) : (SS / FKT - 1);

    #pragma unroll
    for (int i = 0; i < 4; i++) {
        int l  = t + i * 256;
        int tk = l >> 4;
        int q4 = l & 15;
        cp16(kbase + (tk * FSB + q4 * 4) * 4, Kp + (long long)tk * DD + q4 * 4);
    }
    #pragma unroll
    for (int i = 0; i < 4; i++) {
        int l  = t + i * 256;
        int d  = l >> 4;
        int t4 = l & 15;
        cp16(vbase + (d * FSB + t4 * 4) * 4, Vp + (((long long)d) << 10) + t4 * 4);
    }
    cp_commit();

    for (int j = 0; j <= jmax; j++) {
        const int cur = j & 1;
        if (j < jmax) {
            const int nxt = cur ^ 1;
            #pragma unroll
            for (int i = 0; i < 4; i++) {
                int l  = t + i * 256;
                int tk = l >> 4;
                int q4 = l & 15;
                cp16(kbase + nxt * stageK + (tk * FSB + q4 * 4) * 4,
                     Kp + (long long)((j + 1) * FKT + tk) * DD + q4 * 4);
            }
            #pragma unroll
            for (int i = 0; i < 4; i++) {
                int l  = t + i * 256;
                int d  = l >> 4;
                int t4 = l & 15;
                cp16(vbase + nxt * stageK + (d * FSB + t4 * 4) * 4,
                     Vp + (((long long)d) << 10) + (j + 1) * FKT + t4 * 4);
            }
            cp_commit();
            cp_wait1();
        } else {
            cp_wait0();
        }
        __syncthreads();

        const float* Kc = Kb + cur * (FKT * FSB);
        const float* Vc = Vb + cur * (FKT * FSB);

        float s[8][4];
        #pragma unroll
        for (int i = 0; i < 8; i++)
            #pragma unroll
            for (int r = 0; r < 4; r++) s[i][r] = 0.f;

        #pragma unroll
        for (int ks = 0; ks < 8; ks++) {
            #pragma unroll
            for (int nt = 0; nt < 8; nt++) {
                unsigned int bf[2];
                bf[0] = __float_as_uint(Kc[(nt * 8 + gr) * FSB + ks * 8 + gc]);
                bf[1] = __float_as_uint(Kc[(nt * 8 + gr) * FSB + ks * 8 + gc + 4]);
                mma_tf32(s[nt], qf[ks], bf);
            }
        }

        float tm0 = -1e30f, tm1 = -1e30f;
        #pragma unroll
        for (int nt = 0; nt < 8; nt++) {
            s[nt][0] *= 0.125f; s[nt][1] *= 0.125f;
            s[nt][2] *= 0.125f; s[nt][3] *= 0.125f;
            if (CAUSAL && j >= 2 * qi) {
                int c0 = j * FKT + nt * 8 + 2 * gc;
                int c1 = c0 + 1;
                if (c0 > rg0) s[nt][0] = -1e30f;
                if (c1 > rg0) s[nt][1] = -1e30f;
                if (c0 > rg1) s[nt][2] = -1e30f;
                if (c1 > rg1) s[nt][3] = -1e30f;
            }
            tm0 = fmaxf(tm0, fmaxf(s[nt][0], s[nt][1]));
            tm1 = fmaxf(tm1, fmaxf(s[nt][2], s[nt][3]));
        }
        tm0 = fmaxf(tm0, __shfl_xor_sync(0xffffffffu, tm0, 1));
        tm0 = fmaxf(tm0, __shfl_xor_sync(0xffffffffu, tm0, 2));
        tm1 = fmaxf(tm1, __shfl_xor_sync(0xffffffffu, tm1, 1));
        tm1 = fmaxf(tm1, __shfl_xor_sync(0xffffffffu, tm1, 2));

        float mn0 = fmaxf(m0, tm0);
        float mn1 = fmaxf(m1, tm1);
        float sc0 = __expf(m0 - mn0);
        float sc1 = __expf(m1 - mn1);
        float ps0 = 0.f, ps1 = 0.f;

        #pragma unroll
        for (int nt = 0; nt < 8; nt++) {
            float p00 = __expf(s[nt][0] - mn0);
            float p01 = __expf(s[nt][1] - mn0);
            float p10 = __expf(s[nt][2] - mn1);
            float p11 = __expf(s[nt][3] - mn1);
            ps0 += p00 + p01;
            ps1 += p10 + p11;
            *(float2*)&Pb[(wrow + gr    ) * FSB + nt * 8 + 2 * gc] = make_float2(p00, p01);
            *(float2*)&Pb[(wrow + gr + 8) * FSB + nt * 8 + 2 * gc] = make_float2(p10, p11);
        }
        ps0 += __shfl_xor_sync(0xffffffffu, ps0, 1);
        ps0 += __shfl_xor_sync(0xffffffffu, ps0, 2);
        ps1 += __shfl_xor_sync(0xffffffffu, ps1, 1);
        ps1 += __shfl_xor_sync(0xffffffffu, ps1, 2);

        l0 = l0 * sc0 + ps0;
        l1 = l1 * sc1 + ps1;
        m0 = mn0; m1 = mn1;

        #pragma unroll
        for (int nt = 0; nt < 8; nt++) {
            o[nt][0] *= sc0; o[nt][1] *= sc0;
            o[nt][2] *= sc1; o[nt][3] *= sc1;
        }
        __syncwarp();

        #pragma unroll
        for (int ks = 0; ks < 8; ks++) {
            unsigned int pf[4];
            pf[0] = __float_as_uint(Pb[(wrow + gr    ) * FSB + ks * 8 + gc]);
            pf[1] = __float_as_uint(Pb[(wrow + gr + 8) * FSB + ks * 8 + gc]);
            pf[2] = __float_as_uint(Pb[(wrow + gr    ) * FSB + ks * 8 + gc + 4]);
            pf[3] = __float_as_uint(Pb[(wrow + gr + 8) * FSB + ks * 8 + gc + 4]);
            #pragma unroll
            for (int nt = 0; nt < 8; nt++) {
                unsigned int bf[2];
                bf[0] = __float_as_uint(Vc[(nt * 8 + gr) * FSB + ks * 8 + gc]);
                bf[1] = __float_as_uint(Vc[(nt * 8 + gr) * FSB + ks * 8 + gc + 4]);
                mma_tf32(o[nt], pf, bf);
            }
        }
        __syncthreads();
    }

    float inv0 = 1.f / l0;
    float inv1 = 1.f / l1;
    #pragma unroll
    for (int nt = 0; nt < 8; nt++) {
        int c = nt * 8 + 2 * gc;
        *(float2*)(Op + (long long)(wrow + gr    ) * DD + c) =
            make_float2(o[nt][0] * inv0, o[nt][1] * inv0);
        *(float2*)(Op + (long long)(wrow + gr + 8) * DD + c) =
            make_float2(o[nt][2] * inv1, o[nt][3] * inv1);
    }
}

// ---------------------------------------------------------------------------
// out = LayerNorm(a + b) * g + beta
// ---------------------------------------------------------------------------
__global__ void __launch_bounds__(256) add_ln_kernel(
    const float* __restrict__ A, const float* __restrict__ Bv,
    const float* __restrict__ g, const float* __restrict__ be,
    float* __restrict__ out)
{
    __shared__ float redS[8];
    __shared__ float redQ[8];
    long long row = blockIdx.x;
    int t = threadIdx.x;

    float4 a = *(const float4*)(A  + row * DD + t * 4);
    float4 b = *(const float4*)(Bv + row * DD + t * 4);
    float4 s;
    s.x = a.x + b.x; s.y = a.y + b.y; s.z = a.z + b.z; s.w = a.w + b.w;

    float sum = s.x + s.y + s.z + s.w;
    float sq  = s.x*s.x + s.y*s.y + s.z*s.z + s.w*s.w;
    #pragma unroll
    for (int o = 16; o > 0; o >>= 1) {
        sum += __shfl_xor_sync(0xffffffffu, sum, o);
        sq  += __shfl_xor_sync(0xffffffffu, sq,  o);
    }
    if ((t & 31) == 0) { redS[t >> 5] = sum; redQ[t >> 5] = sq; }
    __syncthreads();
    sum = 0.f; sq = 0.f;
    #pragma unroll
    for (int i = 0; i < 8; i++) { sum += redS[i]; sq += redQ[i]; }

    float mean = sum * (1.0f / DD);
    float var  = sq  * (1.0f / DD) - mean * mean;
    float rstd = rsqrtf(var + 1e-5f);

    float4 gg = *(const float4*)(g  + t * 4);
    float4 bb = *(const float4*)(be + t * 4);
    float4 o;
    o.x = (s.x - mean) * rstd * gg.x + bb.x;
    o.y = (s.y - mean) * rstd * gg.y + bb.y;
    o.z = (s.z - mean) * rstd * gg.z + bb.z;
    o.w = (s.w - mean) * rstd * gg.w + bb.w;
    *(float4*)(out + row * DD + t * 4) = o;
}

// ---------------------------------------------------------------------------
// Launch
// ---------------------------------------------------------------------------
extern "C" void kernel_launch(void* const* d_in, const int* in_sizes, int n_in,
                              void* d_out, int out_size)
{
    const float* x        = (const float*)d_in[0];
    const float* enc      = (const float*)d_in[1];
    const float* sa_wq    = (const float*)d_in[4];
    const float* sa_bq    = (const float*)d_in[5];
    const float* sa_wk    = (const float*)d_in[6];
    const float* sa_bk    = (const float*)d_in[7];
    const float* sa_wv    = (const float*)d_in[8];
    const float* sa_bv    = (const float*)d_in[9];
    const float* sa_wo    = (const float*)d_in[10];
    const float* sa_bo    = (const float*)d_in[11];
    const float* ca_in_w  = (const float*)d_in[12];
    const float* ca_in_b  = (const float*)d_in[13];
    const float* ca_out_w = (const float*)d_in[14];
    const float* ca_out_b = (const float*)d_in[15];
    const float* ff_w1    = (const float*)d_in[16];
    const float* ff_b1    = (const float*)d_in[17];
    const float* ff_w2    = (const float*)d_in[18];
    const float* ff_b2    = (const float*)d_in[19];
    const float* n1_g     = (const float*)d_in[20];
    const float* n1_b     = (const float*)d_in[21];
    const float* n2_g     = (const float*)d_in[22];
    const float* n2_b     = (const float*)d_in[23];
    const float* n3_g     = (const float*)d_in[24];
    const float* n3_b     = (const float*)d_in[25];
    float* out = (float*)d_out;

    float *q, *k, *v, *k2, *v2, *attn, *tmp, *x1, *x2, *hid;
    cudaGetSymbolAddress((void**)&q,    g_q);
    cudaGetSymbolAddress((void**)&k,    g_k);
    cudaGetSymbolAddress((void**)&v,    g_v);
    cudaGetSymbolAddress((void**)&k2,   g_k2);
    cudaGetSymbolAddress((void**)&v2,   g_v2);
    cudaGetSymbolAddress((void**)&attn, g_attn);
    cudaGetSymbolAddress((void**)&tmp,  g_tmp);
    cudaGetSymbolAddress((void**)&x1,   g_x1);
    cudaGetSymbolAddress((void**)&x2,   g_x2);
    cudaGetSymbolAddress((void**)&hid,  g_hidden);

    const int SMEM_TC = 3 * (128 + 128) * 36 * 4;       // 110592 bytes
    const int SMEM_FL = (4 * FKT + FQT) * FSB * 4;      // 104448 bytes
    cudaFuncSetAttribute(gemm_tc<false,false,false>,
                         cudaFuncAttributeMaxDynamicSharedMemorySize, SMEM_TC);
    cudaFuncSetAttribute(gemm_tc<true,false,false>,
                         cudaFuncAttributeMaxDynamicSharedMemorySize, SMEM_TC);
    cudaFuncSetAttribute(gemm_tc<false,true,false>,
                         cudaFuncAttributeMaxDynamicSharedMemorySize, SMEM_TC);
    cudaFuncSetAttribute(gemm_qkv5,
                         cudaFuncAttributeMaxDynamicSharedMemorySize, SMEM_TC);
    cudaFuncSetAttribute(flash_attn<true>,
                         cudaFuncAttributeMaxDynamicSharedMemorySize, SMEM_FL);
    cudaFuncSetAttribute(flash_attn<false>,
                         cudaFuncAttributeMaxDynamicSharedMemorySize, SMEM_FL);

    dim3 blk(256);
    dim3 gProj(DD/128, MM/128, 1);
    dim3 gQKV5(DD/128, MM/128, 5);
    dim3 gFF1(DFFN/128, MM/128, 1);
    dim3 gFlash(SS/128, BH, 1);

    // ---- Merged independent projections (SA q,k,v + CA k,v) ----
    P5 p;
    p.A[0] = x;   p.B[0] = sa_wq;                    p.bias[0] = sa_bq;          p.C[0] = q;  p.trans[0] = 0;
    p.A[1] = x;   p.B[1] = sa_wk;                    p.bias[1] = sa_bk;          p.C[1] = k;  p.trans[1] = 0;
    p.A[2] = x;   p.B[2] = sa_wv;                    p.bias[2] = sa_bv;          p.C[2] = v;  p.trans[2] = 1;
    p.A[3] = enc; p.B[3] = ca_in_w + (long long)DD*DD;  p.bias[3] = ca_in_b + DD;   p.C[3] = k2; p.trans[3] = 0;
    p.A[4] = enc; p.B[4] = ca_in_w + 2ll*DD*DD;         p.bias[4] = ca_in_b + 2*DD; p.C[4] = v2; p.trans[4] = 1;
    gemm_qkv5<<<gQKV5, blk, SMEM_TC>>>(p, DD);

    // ---- Self-attention ----
    flash_attn<true><<<gFlash, blk, SMEM_FL>>>(q, k, v, attn);
    gemm_tc<false,false,false><<<gProj, blk, SMEM_TC>>>(attn, DD, sa_wo, DD, sa_bo, tmp, DD, DD);
    add_ln_kernel<<<MM, blk>>>(x, tmp, n1_g, n1_b, x1);

    // ---- Cross-attention ----
    gemm_tc<false,true,false><<<gProj, blk, SMEM_TC>>>(x1, DD, ca_in_w, DD, ca_in_b, q, DD, DD);
    flash_attn<false><<<gFlash, blk, SMEM_FL>>>(q, k2, v2, attn);
    gemm_tc<false,false,false><<<gProj, blk, SMEM_TC>>>(attn, DD, ca_out_w, DD, ca_out_b, tmp, DD, DD);
    add_ln_kernel<<<MM, blk>>>(x1, tmp, n2_g, n2_b, x2);

    // ---- FFN ----
    gemm_tc<true,false,false ><<<gFF1,  blk, SMEM_TC>>>(x2,  DD,   ff_w1, DD,   ff_b1, hid, DFFN, DD);
    gemm_tc<false,false,false><<<gProj, blk, SMEM_TC>>>(hid, DFFN, ff_w2, DFFN, ff_b2, tmp, DD,   DFFN);
    add_ln_kernel<<<MM, blk>>>(x2, tmp, n3_g, n3_b, out);
}

// round 13
// speedup vs baseline: 1.0772x; 1.0772x over previous
#include <cuda_runtime.h>
#include <cuda_bf16.h>
#include <cstdint>
#include <math.h>

// Problem constants
#define BB   4
#define SS   1024
#define DD   1024
#define HH   16
#define DKK  64
#define DFFN 4096
#define MM   (BB*SS)        // 4096 token rows
#define BH   (BB*HH)        // 64
#define MI   (1024*1024)

// ---------------------------------------------------------------------------
// Scratch
// ---------------------------------------------------------------------------
__device__ float g_q[MM*DD];
__device__ float g_k[MM*DD];
__device__ float g_v[MM*DD];      // V TRANSPOSED: [(b*1024+col)*1024 + t]
__device__ float g_k2[MM*DD];     // CA k
__device__ float g_v2[MM*DD];     // CA v (transposed)
__device__ float g_attn[MM*DD];
__device__ float g_tmp[MM*DD];
__device__ float g_x1[MM*DD];
__device__ float g_x1r[MM*DD];    // tf32-rounded copy of x1 (GEMM operand)
__device__ float g_x2[MM*DD];
__device__ float g_x2r[MM*DD];    // tf32-rounded copy of x2
__device__ float g_hidden[(long long)MM*DFFN];    // 67MB
__device__ float g_round[24ll*MI];                // rounded inputs/weights, 96MB

// ---------------------------------------------------------------------------
// helpers
// ---------------------------------------------------------------------------
__device__ __forceinline__ unsigned int f2tf32(float f) {
    unsigned int r;
    asm("cvt.rna.tf32.f32 %0, %1;" : "=r"(r) : "f"(f));
    return r;
}

__device__ __forceinline__ void mma_tf32(float (&c)[4],
                                         const unsigned int (&a)[4],
                                         const unsigned int (&b)[2]) {
    asm volatile(
        "mma.sync.aligned.m16n8k8.row.col.f32.tf32.tf32.f32 "
        "{%0,%1,%2,%3}, {%4,%5,%6,%7}, {%8,%9}, {%0,%1,%2,%3};"
        : "+f"(c[0]), "+f"(c[1]), "+f"(c[2]), "+f"(c[3])
        : "r"(a[0]), "r"(a[1]), "r"(a[2]), "r"(a[3]),
          "r"(b[0]), "r"(b[1]));
}

__device__ __forceinline__ void cp16(unsigned int saddr, const float* g) {
    asm volatile("cp.async.cg.shared.global [%0], [%1], 16;\n" :: "r"(saddr), "l"(g));
}
__device__ __forceinline__ void cp_commit() {
    asm volatile("cp.async.commit_group;\n" ::);
}
__device__ __forceinline__ void cp_wait1() {
    asm volatile("cp.async.wait_group 1;\n" ::);
}
__device__ __forceinline__ void cp_wait0() {
    asm volatile("cp.async.wait_group 0;\n" ::);
}

// ---------------------------------------------------------------------------
// Batched tf32 rounding pass: dst[z] = round_tf32(src[z]) elementwise.
// ---------------------------------------------------------------------------
#define RN 10
struct RTab {
    const float* src[RN];
    float*       dst[RN];
    int          n4[RN];     // number of float4 chunks
};

__global__ void __launch_bounds__(256) round_all(RTab rt)
{
    int z = blockIdx.z;
    int i = blockIdx.x * 256 + threadIdx.x;
    if (i >= rt.n4[z]) return;
    float4 v = ((const float4*)rt.src[z])[i];
    v.x = __uint_as_float(f2tf32(v.x));
    v.y = __uint_as_float(f2tf32(v.y));
    v.z = __uint_as_float(f2tf32(v.z));
    v.w = __uint_as_float(f2tf32(v.w));
    ((float4*)rt.dst[z])[i] = v;
}

// Per-z operand table for the merged projection launch (passed by value).
struct P5 {
    const float* A[5];
    const float* B[5];
    const float* bias[5];
    float*       C[5];
    int          trans[5];
};

// ---------------------------------------------------------------------------
// Core 128x128 tf32 GEMM body (TN), 3-stage cp.async pipeline, wait_group 1.
// ALL operands must be pre-rounded to the tf32 grid: fragments are loaded as
// raw bits (no cvt in the inner loop).
// ---------------------------------------------------------------------------
template<bool RELU, bool ROUND_OUT>
__device__ __forceinline__ void gemm_body_128(
    const float* __restrict__ A, const float* __restrict__ B,
    const float* __restrict__ bias, float* __restrict__ C,
    int lda, int ldb, int ldc, int K, int trans_out, float* smem)
{
    constexpr int BM = 128, BN = 128, WM = 64, WN = 32;
    constexpr int MT = WM / 16;       // 4
    constexpr int NT = WN / 8;        // 4
    constexpr int NWN = BN / WN;      // 4

    float* AsBase = smem;                    // 3 stages of BM*36
    float* BsBase = smem + 3 * BM * 36;      // 3 stages of BN*36

    const int row0 = blockIdx.y * BM;
    const int col0 = blockIdx.x * BN;
    const int t    = threadIdx.x;
    const int w    = t >> 5;
    const int lane = t & 31;
    const int wm   = w / NWN;
    const int wn   = w % NWN;
    const int gr   = lane >> 2;
    const int gc   = lane & 3;

    const int m0 = t >> 3;
    const int kq = t & 7;

    const float* gA = A + (long long)(row0 + m0) * lda + kq * 4;
    const float* gB = B + (long long)(col0 + m0) * ldb + kq * 4;

    unsigned int aBase = (unsigned int)__cvta_generic_to_shared(AsBase);
    unsigned int bBase = (unsigned int)__cvta_generic_to_shared(BsBase);
    constexpr unsigned int stageA = BM * 36 * 4;
    constexpr unsigned int stageB = BN * 36 * 4;

    float acc[MT][NT][4];
    #pragma unroll
    for (int i = 0; i < MT; i++)
        #pragma unroll
        for (int j = 0; j < NT; j++)
            #pragma unroll
            for (int r = 0; r < 4; r++) acc[i][j][r] = 0.f;

    const int nk = K >> 5;   // 32 or 128: both == 2 (mod 3)

    // prologue: tile 0 -> stage 0 (G0), tile 1 -> stage 1 (G1)
    #pragma unroll
    for (int i = 0; i < BM / 32; i++)
        cp16(aBase + ((m0 + 32 * i) * 36 + kq * 4) * 4, gA + (long long)(32 * i) * lda);
    #pragma unroll
    for (int i = 0; i < BN / 32; i++)
        cp16(bBase + ((m0 + 32 * i) * 36 + kq * 4) * 4, gB + (long long)(32 * i) * ldb);
    cp_commit();
    #pragma unroll
    for (int i = 0; i < BM / 32; i++)
        cp16(aBase + stageA + ((m0 + 32 * i) * 36 + kq * 4) * 4, gA + 32 + (long long)(32 * i) * lda);
    #pragma unroll
    for (int i = 0; i < BN / 32; i++)
        cp16(bBase + stageB + ((m0 + 32 * i) * 36 + kq * 4) * 4, gB + 32 + (long long)(32 * i) * ldb);
    cp_commit();

#define PREFETCH_TILE(W)                                                          \
    {                                                                             \
        const float* gA2 = gA + (it + 2) * 32;                                    \
        const float* gB2 = gB + (it + 2) * 32;                                    \
        _Pragma("unroll")                                                         \
        for (int i = 0; i < BM / 32; i++)                                         \
            cp16(aBase + (W) * stageA + ((m0 + 32 * i) * 36 + kq * 4) * 4,        \
                 gA2 + (long long)(32 * i) * lda);                                \
        _Pragma("unroll")                                                         \
        for (int i = 0; i < BN / 32; i++)                                         \
            cp16(bBase + (W) * stageB + ((m0 + 32 * i) * 36 + kq * 4) * 4,        \
                 gB2 + (long long)(32 * i) * ldb);                                \
    }

#define COMPUTE_TILE(S)                                                           \
    {                                                                             \
        const float* Acur = AsBase + (S) * (BM * 36);                             \
        const float* Bcur = BsBase + (S) * (BN * 36);                             \
        _Pragma("unroll")                                                         \
        for (int ks = 0; ks < 32; ks += 8) {                                      \
            unsigned int af[MT][4];                                               \
            unsigned int bf[NT][2];                                               \
            _Pragma("unroll")                                                     \
            for (int mt = 0; mt < MT; mt++) {                                     \
                int r = wm * WM + mt * 16 + gr;                                   \
                af[mt][0] = __float_as_uint(Acur[(r    ) * 36 + ks + gc]);        \
                af[mt][1] = __float_as_uint(Acur[(r + 8) * 36 + ks + gc]);        \
                af[mt][2] = __float_as_uint(Acur[(r    ) * 36 + ks + gc + 4]);    \
                af[mt][3] = __float_as_uint(Acur[(r + 8) * 36 + ks + gc + 4]);    \
            }                                                                     \
            _Pragma("unroll")                                                     \
            for (int nt = 0; nt < NT; nt++) {                                     \
                int n = wn * WN + nt * 8 + gr;                                    \
                bf[nt][0] = __float_as_uint(Bcur[n * 36 + ks + gc]);              \
                bf[nt][1] = __float_as_uint(Bcur[n * 36 + ks + gc + 4]);          \
            }                                                                     \
            _Pragma("unroll")                                                     \
            for (int mt = 0; mt < MT; mt++)                                       \
                _Pragma("unroll")                                                 \
                for (int nt = 0; nt < NT; nt++)                                   \
                    mma_tf32(acc[mt][nt], af[mt], bf[nt]);                        \
        }                                                                         \
    }

#define GEMM_STEP(S, W)                                                           \
    {                                                                             \
        cp_wait1();                                                               \
        __syncthreads();                                                          \
        if (it + 2 < nk) PREFETCH_TILE(W);                                        \
        cp_commit();                                                              \
        COMPUTE_TILE(S);                                                          \
        it++;                                                                     \
    }

    int it = 0;
    while (it + 3 <= nk) {
        GEMM_STEP(0, 2)
        GEMM_STEP(1, 0)
        GEMM_STEP(2, 1)
    }
    // nk % 3 == 2 for K=1024 and K=4096: remainder tiles at stages 0, 1
    GEMM_STEP(0, 2)
    GEMM_STEP(1, 0)

#undef GEMM_STEP
#undef COMPUTE_TILE
#undef PREFETCH_TILE

    // ---- Epilogue ----
    #pragma unroll
    for (int mt = 0; mt < MT; mt++) {
        #pragma unroll
        for (int nt = 0; nt < NT; nt++) {
            int row = row0 + wm * WM + mt * 16 + gr;
            int col = col0 + wn * WN + nt * 8 + gc * 2;
            float b0 = 0.f, b1 = 0.f;
            if (bias) { b0 = bias[col]; b1 = bias[col + 1]; }
            float v0 = acc[mt][nt][0] + b0;
            float v1 = acc[mt][nt][1] + b1;
            float v2 = acc[mt][nt][2] + b0;
            float v3 = acc[mt][nt][3] + b1;
            if (RELU) {
                v0 = fmaxf(v0, 0.f); v1 = fmaxf(v1, 0.f);
                v2 = fmaxf(v2, 0.f); v3 = fmaxf(v3, 0.f);
            }
            if (ROUND_OUT) {
                v0 = __uint_as_float(f2tf32(v0));
                v1 = __uint_as_float(f2tf32(v1));
                v2 = __uint_as_float(f2tf32(v2));
                v3 = __uint_as_float(f2tf32(v3));
            }
            if (trans_out) {
                int rb = row >> 10;
                int tt = row & 1023;
                long long a0 = ((long long)(rb * 1024 + col) << 10) + tt;
                C[a0]            = v0;
                C[a0 + 1024]     = v1;
                C[a0 + 8]        = v2;
                C[a0 + 1024 + 8] = v3;
            } else {
                *(float2*)(C + (long long)row * ldc + col)       = make_float2(v0, v1);
                *(float2*)(C + (long long)(row + 8) * ldc + col) = make_float2(v2, v3);
            }
        }
    }
}

// Generic single-GEMM wrapper.
template<bool RELU, bool ROUND_OUT, bool TRANS_OUT>
__global__ void __launch_bounds__(256, 2) gemm_tc(
    const float* __restrict__ A, int lda,
    const float* __restrict__ B, int ldb,
    const float* __restrict__ bias,
    float* __restrict__ C, int ldc, int K)
{
    extern __shared__ float smem[];
    gemm_body_128<RELU, ROUND_OUT>(A, B, bias, C, lda, ldb, ldc, K,
                                   TRANS_OUT ? 1 : 0, smem);
}

// Merged independent projections: z selects operands (SAq,SAk,SAv,CAk,CAv).
__global__ void __launch_bounds__(256, 2) gemm_qkv5(P5 p, int K)
{
    extern __shared__ float smem[];
    const int z = blockIdx.z;
    gemm_body_128<false, true>(p.A[z], p.B[z], p.bias[z], p.C[z],
                               DD, DD, DD, K, p.trans[z], smem);
}

// ---------------------------------------------------------------------------
// Flash attention with cp.async double-buffered K/V tiles.
// Epilogue rounds O to the tf32 grid (consumed raw by out-proj GEMM).
// ---------------------------------------------------------------------------
#define FQT 128
#define FKT 64
#define FSB 68

template<bool CAUSAL>
__global__ void __launch_bounds__(256, 2) flash_attn(
    const float* __restrict__ Q, const float* __restrict__ K,
    const float* __restrict__ VT, float* __restrict__ O)
{
    extern __shared__ float sm[];
    float* Kb = sm;                       // [2][FKT][FSB]
    float* Vb = sm + 2 * FKT * FSB;       // [2][64][FSB]
    float* Pb = sm + 4 * FKT * FSB;       // [FQT][FSB]

    const int qi = CAUSAL ? ((int)gridDim.x - 1 - (int)blockIdx.x) : (int)blockIdx.x;
    const int bh = blockIdx.y;
    const int b  = bh >> 4;
    const int h  = bh & 15;

    const int t    = threadIdx.x;
    const int w    = t >> 5;
    const int lane = t & 31;
    const int gr   = lane >> 2;
    const int gc   = lane & 3;
    const int wrow = w * 16;

    const long long rowbase = (long long)b * SS;
    const float* Qp = Q + (rowbase + qi * FQT) * DD + h * 64;
    const float* Kp = K + rowbase * DD + h * 64;
    const float* Vp = VT + (((long long)(b * 1024 + h * 64)) << 10);
    float* Op = O + (rowbase + qi * FQT) * DD + h * 64;

    unsigned int kbase = (unsigned int)__cvta_generic_to_shared(Kb);
    unsigned int vbase = (unsigned int)__cvta_generic_to_shared(Vb);
    constexpr unsigned int stageK = FKT * FSB * 4;

    #pragma unroll
    for (int i = 0; i < 8; i++) {
        int l  = t + i * 256;
        int m  = l >> 4;
        int q4 = l & 15;
        float4 v = *(const float4*)(Qp + (long long)m * DD + q4 * 4);
        *(float4*)&Pb[m * FSB + q4 * 4] = v;
    }
    __syncthreads();

    unsigned int qf[8][4];
    #pragma unroll
    for (int ks = 0; ks < 8; ks++) {
        qf[ks][0] = __float_as_uint(Pb[(wrow + gr    ) * FSB + ks * 8 + gc]);
        qf[ks][1] = __float_as_uint(Pb[(wrow + gr + 8) * FSB + ks * 8 + gc]);
        qf[ks][2] = __float_as_uint(Pb[(wrow + gr    ) * FSB + ks * 8 + gc + 4]);
        qf[ks][3] = __float_as_uint(Pb[(wrow + gr + 8) * FSB + ks * 8 + gc + 4]);
    }
    __syncthreads();

    float o[8][4];
    #pragma unroll
    for (int i = 0; i < 8; i++)
        #pragma unroll
        for (int r = 0; r < 4; r++) o[i][r] = 0.f;
    float m0 = -1e30f, m1 = -1e30f, l0 = 0.f, l1 = 0.f;

    const int rg0 = qi * FQT + wrow + gr;
    const int rg1 = rg0 + 8;
    const int jmax = CAUSAL ? (2 * qi + 1) : (SS / FKT - 1);

    #pragma unroll
    for (int i = 0; i < 4; i++) {
        int l  = t + i * 256;
        int tk = l >> 4;
        int q4 = l & 15;
        cp16(kbase + (tk * FSB + q4 * 4) * 4, Kp + (long long)tk * DD + q4 * 4);
    }
    #pragma unroll
    for (int i = 0; i < 4; i++) {
        int l  = t + i * 256;
        int d  = l >> 4;
        int t4 = l & 15;
        cp16(vbase + (d * FSB + t4 * 4) * 4, Vp + (((long long)d) << 10) + t4 * 4);
    }
    cp_commit();

    for (int j = 0; j <= jmax; j++) {
        const int cur = j & 1;
        if (j < jmax) {
            const int nxt = cur ^ 1;
            #pragma unroll
            for (int i = 0; i < 4; i++) {
                int l  = t + i * 256;
                int tk = l >> 4;
                int q4 = l & 15;
                cp16(kbase + nxt * stageK + (tk * FSB + q4 * 4) * 4,
                     Kp + (long long)((j + 1) * FKT + tk) * DD + q4 * 4);
            }
            #pragma unroll
            for (int i = 0; i < 4; i++) {
                int l  = t + i * 256;
                int d  = l >> 4;
                int t4 = l & 15;
                cp16(vbase + nxt * stageK + (d * FSB + t4 * 4) * 4,
                     Vp + (((long long)d) << 10) + (j + 1) * FKT + t4 * 4);
            }
            cp_commit();
            cp_wait1();
        } else {
            cp_wait0();
        }
        __syncthreads();

        const float* Kc = Kb + cur * (FKT * FSB);
        const float* Vc = Vb + cur * (FKT * FSB);

        float s[8][4];
        #pragma unroll
        for (int i = 0; i < 8; i++)
            #pragma unroll
            for (int r = 0; r < 4; r++) s[i][r] = 0.f;

        #pragma unroll
        for (int ks = 0; ks < 8; ks++) {
            #pragma unroll
            for (int nt = 0; nt < 8; nt++) {
                unsigned int bf[2];
                bf[0] = __float_as_uint(Kc[(nt * 8 + gr) * FSB + ks * 8 + gc]);
                bf[1] = __float_as_uint(Kc[(nt * 8 + gr) * FSB + ks * 8 + gc + 4]);
                mma_tf32(s[nt], qf[ks], bf);
            }
        }

        float tm0 = -1e30f, tm1 = -1e30f;
        #pragma unroll
        for (int nt = 0; nt < 8; nt++) {
            s[nt][0] *= 0.125f; s[nt][1] *= 0.125f;
            s[nt][2] *= 0.125f; s[nt][3] *= 0.125f;
            if (CAUSAL && j >= 2 * qi) {
                int c0 = j * FKT + nt * 8 + 2 * gc;
                int c1 = c0 + 1;
                if (c0 > rg0) s[nt][0] = -1e30f;
                if (c1 > rg0) s[nt][1] = -1e30f;
                if (c0 > rg1) s[nt][2] = -1e30f;
                if (c1 > rg1) s[nt][3] = -1e30f;
            }
            tm0 = fmaxf(tm0, fmaxf(s[nt][0], s[nt][1]));
            tm1 = fmaxf(tm1, fmaxf(s[nt][2], s[nt][3]));
        }
        tm0 = fmaxf(tm0, __shfl_xor_sync(0xffffffffu, tm0, 1));
        tm0 = fmaxf(tm0, __shfl_xor_sync(0xffffffffu, tm0, 2));
        tm1 = fmaxf(tm1, __shfl_xor_sync(0xffffffffu, tm1, 1));
        tm1 = fmaxf(tm1, __shfl_xor_sync(0xffffffffu, tm1, 2));

        float mn0 = fmaxf(m0, tm0);
        float mn1 = fmaxf(m1, tm1);
        float sc0 = __expf(m0 - mn0);
        float sc1 = __expf(m1 - mn1);
        float ps0 = 0.f, ps1 = 0.f;

        #pragma unroll
        for (int nt = 0; nt < 8; nt++) {
            float p00 = __expf(s[nt][0] - mn0);
            float p01 = __expf(s[nt][1] - mn0);
            float p10 = __expf(s[nt][2] - mn1);
            float p11 = __expf(s[nt][3] - mn1);
            ps0 += p00 + p01;
            ps1 += p10 + p11;
            *(float2*)&Pb[(wrow + gr    ) * FSB + nt * 8 + 2 * gc] = make_float2(p00, p01);
            *(float2*)&Pb[(wrow + gr + 8) * FSB + nt * 8 + 2 * gc] = make_float2(p10, p11);
        }
        ps0 += __shfl_xor_sync(0xffffffffu, ps0, 1);
        ps0 += __shfl_xor_sync(0xffffffffu, ps0, 2);
        ps1 += __shfl_xor_sync(0xffffffffu, ps1, 1);
        ps1 += __shfl_xor_sync(0xffffffffu, ps1, 2);

        l0 = l0 * sc0 + ps0;
        l1 = l1 * sc1 + ps1;
        m0 = mn0; m1 = mn1;

        #pragma unroll
        for (int nt = 0; nt < 8; nt++) {
            o[nt][0] *= sc0; o[nt][1] *= sc0;
            o[nt][2] *= sc1; o[nt][3] *= sc1;
        }
        __syncwarp();

        #pragma unroll
        for (int ks = 0; ks < 8; ks++) {
            unsigned int pf[4];
            pf[0] = __float_as_uint(Pb[(wrow + gr    ) * FSB + ks * 8 + gc]);
            pf[1] = __float_as_uint(Pb[(wrow + gr + 8) * FSB + ks * 8 + gc]);
            pf[2] = __float_as_uint(Pb[(wrow + gr    ) * FSB + ks * 8 + gc + 4]);
            pf[3] = __float_as_uint(Pb[(wrow + gr + 8) * FSB + ks * 8 + gc + 4]);
            #pragma unroll
            for (int nt = 0; nt < 8; nt++) {
                unsigned int bf[2];
                bf[0] = __float_as_uint(Vc[(nt * 8 + gr) * FSB + ks * 8 + gc]);
                bf[1] = __float_as_uint(Vc[(nt * 8 + gr) * FSB + ks * 8 + gc + 4]);
                mma_tf32(o[nt], pf, bf);
            }
        }
        __syncthreads();
    }

    float inv0 = 1.f / l0;
    float inv1 = 1.f / l1;
    #pragma unroll
    for (int nt = 0; nt < 8; nt++) {
        int c = nt * 8 + 2 * gc;
        *(float2*)(Op + (long long)(wrow + gr    ) * DD + c) =
            make_float2(__uint_as_float(f2tf32(o[nt][0] * inv0)),
                        __uint_as_float(f2tf32(o[nt][1] * inv0)));
        *(float2*)(Op + (long long)(wrow + gr + 8) * DD + c) =
            make_float2(__uint_as_float(f2tf32(o[nt][2] * inv1)),
                        __uint_as_float(f2tf32(o[nt][3] * inv1)));
    }
}

// ---------------------------------------------------------------------------
// out = LayerNorm(a + b) * g + beta ; optional tf32-rounded second output.
// ---------------------------------------------------------------------------
__global__ void __launch_bounds__(256) add_ln_kernel(
    const float* __restrict__ A, const float* __restrict__ Bv,
    const float* __restrict__ g, const float* __restrict__ be,
    float* __restrict__ out, float* __restrict__ out_r)
{
    __shared__ float redS[8];
    __shared__ float redQ[8];
    long long row = blockIdx.x;
    int t = threadIdx.x;

    float4 a = *(const float4*)(A  + row * DD + t * 4);
    float4 b = *(const float4*)(Bv + row * DD + t * 4);
    float4 s;
    s.x = a.x + b.x; s.y = a.y + b.y; s.z = a.z + b.z; s.w = a.w + b.w;

    float sum = s.x + s.y + s.z + s.w;
    float sq  = s.x*s.x + s.y*s.y + s.z*s.z + s.w*s.w;
    #pragma unroll
    for (int o = 16; o > 0; o >>= 1) {
        sum += __shfl_xor_sync(0xffffffffu, sum, o);
        sq  += __shfl_xor_sync(0xffffffffu, sq,  o);
    }
    if ((t & 31) == 0) { redS[t >> 5] = sum; redQ[t >> 5] = sq; }
    __syncthreads();
    sum = 0.f; sq = 0.f;
    #pragma unroll
    for (int i = 0; i < 8; i++) { sum += redS[i]; sq += redQ[i]; }

    float mean = sum * (1.0f / DD);
    float var  = sq  * (1.0f / DD) - mean * mean;
    float rstd = rsqrtf(var + 1e-5f);

    float4 gg = *(const float4*)(g  + t * 4);
    float4 bb = *(const float4*)(be + t * 4);
    float4 o;
    o.x = (s.x - mean) * rstd * gg.x + bb.x;
    o.y = (s.y - mean) * rstd * gg.y + bb.y;
    o.z = (s.z - mean) * rstd * gg.z + bb.z;
    o.w = (s.w - mean) * rstd * gg.w + bb.w;
    *(float4*)(out + row * DD + t * 4) = o;
    if (out_r) {
        float4 r;
        r.x = __uint_as_float(f2tf32(o.x));
        r.y = __uint_as_float(f2tf32(o.y));
        r.z = __uint_as_float(f2tf32(o.z));
        r.w = __uint_as_float(f2tf32(o.w));
        *(float4*)(out_r + row * DD + t * 4) = r;
    }
}

// ---------------------------------------------------------------------------
// Launch
// ---------------------------------------------------------------------------
extern "C" void kernel_launch(void* const* d_in, const int* in_sizes, int n_in,
                              void* d_out, int out_size)
{
    const float* x        = (const float*)d_in[0];
    const float* enc      = (const float*)d_in[1];
    const float* sa_wq    = (const float*)d_in[4];
    const float* sa_bq    = (const float*)d_in[5];
    const float* sa_wk    = (const float*)d_in[6];
    const float* sa_bk    = (const float*)d_in[7];
    const float* sa_wv    = (const float*)d_in[8];
    const float* sa_bv    = (const float*)d_in[9];
    const float* sa_wo    = (const float*)d_in[10];
    const float* sa_bo    = (const float*)d_in[11];
    const float* ca_in_w  = (const float*)d_in[12];
    const float* ca_in_b  = (const float*)d_in[13];
    const float* ca_out_w = (const float*)d_in[14];
    const float* ca_out_b = (const float*)d_in[15];
    const float* ff_w1    = (const float*)d_in[16];
    const float* ff_b1    = (const float*)d_in[17];
    const float* ff_w2    = (const float*)d_in[18];
    const float* ff_b2    = (const float*)d_in[19];
    const float* n1_g     = (const float*)d_in[20];
    const float* n1_b     = (const float*)d_in[21];
    const float* n2_g     = (const float*)d_in[22];
    const float* n2_b     = (const float*)d_in[23];
    const float* n3_g     = (const float*)d_in[24];
    const float* n3_b     = (const float*)d_in[25];
    float* out = (float*)d_out;

    float *q, *k, *v, *k2, *v2, *attn, *tmp, *x1, *x1r, *x2, *x2r, *hid, *rb;
    cudaGetSymbolAddress((void**)&q,    g_q);
    cudaGetSymbolAddress((void**)&k,    g_k);
    cudaGetSymbolAddress((void**)&v,    g_v);
    cudaGetSymbolAddress((void**)&k2,   g_k2);
    cudaGetSymbolAddress((void**)&v2,   g_v2);
    cudaGetSymbolAddress((void**)&attn, g_attn);
    cudaGetSymbolAddress((void**)&tmp,  g_tmp);
    cudaGetSymbolAddress((void**)&x1,   g_x1);
    cudaGetSymbolAddress((void**)&x1r,  g_x1r);
    cudaGetSymbolAddress((void**)&x2,   g_x2);
    cudaGetSymbolAddress((void**)&x2r,  g_x2r);
    cudaGetSymbolAddress((void**)&hid,  g_hidden);
    cudaGetSymbolAddress((void**)&rb,   g_round);

    // rounded-copy layout inside g_round (units of 1M floats)
    float* x_r    = rb;
    float* enc_r  = rb + 4ll*MI;
    float* wq_r   = rb + 8ll*MI;
    float* wk_r   = rb + 9ll*MI;
    float* wv_r   = rb + 10ll*MI;
    float* wo_r   = rb + 11ll*MI;
    float* caw_r  = rb + 12ll*MI;   // 3M floats (q,k,v stacked)
    float* cao_r  = rb + 15ll*MI;
    float* ffw1_r = rb + 16ll*MI;
    float* ffw2_r = rb + 20ll*MI;

    const int SMEM_TC = 3 * (128 + 128) * 36 * 4;       // 110592 bytes
    const int SMEM_FL = (4 * FKT + FQT) * FSB * 4;      // 104448 bytes
    cudaFuncSetAttribute(gemm_tc<false,false,false>,
                         cudaFuncAttributeMaxDynamicSharedMemorySize, SMEM_TC);
    cudaFuncSetAttribute(gemm_tc<true,true,false>,
                         cudaFuncAttributeMaxDynamicSharedMemorySize, SMEM_TC);
    cudaFuncSetAttribute(gemm_tc<false,true,false>,
                         cudaFuncAttributeMaxDynamicSharedMemorySize, SMEM_TC);
    cudaFuncSetAttribute(gemm_qkv5,
                         cudaFuncAttributeMaxDynamicSharedMemorySize, SMEM_TC);
    cudaFuncSetAttribute(flash_attn<true>,
                         cudaFuncAttributeMaxDynamicSharedMemorySize, SMEM_FL);
    cudaFuncSetAttribute(flash_attn<false>,
                         cudaFuncAttributeMaxDynamicSharedMemorySize, SMEM_FL);

    dim3 blk(256);
    dim3 gProj(DD/128, MM/128, 1);
    dim3 gQKV5(DD/128, MM/128, 5);
    dim3 gFF1(DFFN/128, MM/128, 1);
    dim3 gFlash(SS/128, BH, 1);

    // ---- Pre-round all read-only GEMM operands to the tf32 grid ----
    RTab rt;
    rt.src[0] = x;        rt.dst[0] = x_r;    rt.n4[0] = 4*MI/4;
    rt.src[1] = enc;      rt.dst[1] = enc_r;  rt.n4[1] = 4*MI/4;
    rt.src[2] = sa_wq;    rt.dst[2] = wq_r;   rt.n4[2] = MI/4;
    rt.src[3] = sa_wk;    rt.dst[3] = wk_r;   rt.n4[3] = MI/4;
    rt.src[4] = sa_wv;    rt.dst[4] = wv_r;   rt.n4[4] = MI/4;
    rt.src[5] = sa_wo;    rt.dst[5] = wo_r;   rt.n4[5] = MI/4;
    rt.src[6] = ca_in_w;  rt.dst[6] = caw_r;  rt.n4[6] = 3*MI/4;
    rt.src[7] = ca_out_w; rt.dst[7] = cao_r;  rt.n4[7] = MI/4;
    rt.src[8] = ff_w1;    rt.dst[8] = ffw1_r; rt.n4[8] = 4*MI/4;
    rt.src[9] = ff_w2;    rt.dst[9] = ffw2_r; rt.n4[9] = 4*MI/4;
    round_all<<<dim3(4096, 1, RN), blk>>>(rt);

    // ---- Merged independent projections (SA q,k,v + CA k,v) ----
    P5 p;
    p.A[0] = x_r;   p.B[0] = wq_r;            p.bias[0] = sa_bq;          p.C[0] = q;  p.trans[0] = 0;
    p.A[1] = x_r;   p.B[1] = wk_r;            p.bias[1] = sa_bk;          p.C[1] = k;  p.trans[1] = 0;
    p.A[2] = x_r;   p.B[2] = wv_r;            p.bias[2] = sa_bv;          p.C[2] = v;  p.trans[2] = 1;
    p.A[3] = enc_r; p.B[3] = caw_r + (long long)DD*DD; p.bias[3] = ca_in_b + DD;   p.C[3] = k2; p.trans[3] = 0;
    p.A[4] = enc_r; p.B[4] = caw_r + 2ll*DD*DD;        p.bias[4] = ca_in_b + 2*DD; p.C[4] = v2; p.trans[4] = 1;
    gemm_qkv5<<<gQKV5, blk, SMEM_TC>>>(p, DD);

    // ---- Self-attention ----
    flash_attn<true><<<gFlash, blk, SMEM_FL>>>(q, k, v, attn);
    gemm_tc<false,false,false><<<gProj, blk, SMEM_TC>>>(attn, DD, wo_r, DD, sa_bo, tmp, DD, DD);
    add_ln_kernel<<<MM, blk>>>(x, tmp, n1_g, n1_b, x1, x1r);

    // ---- Cross-attention ----
    gemm_tc<false,true,false><<<gProj, blk, SMEM_TC>>>(x1r, DD, caw_r, DD, ca_in_b, q, DD, DD);
    flash_attn<false><<<gFlash, blk, SMEM_FL>>>(q, k2, v2, attn);
    gemm_tc<false,false,false><<<gProj, blk, SMEM_TC>>>(attn, DD, cao_r, DD, ca_out_b, tmp, DD, DD);
    add_ln_kernel<<<MM, blk>>>(x1, tmp, n2_g, n2_b, x2, x2r);

    // ---- FFN ----
    gemm_tc<true,true,false  ><<<gFF1,  blk, SMEM_TC>>>(x2r, DD,   ffw1_r, DD,   ff_b1, hid, DFFN, DD);
    gemm_tc<false,false,false><<<gProj, blk, SMEM_TC>>>(hid, DFFN, ffw2_r, DFFN, ff_b2, tmp, DD,   DFFN);
    add_ln_kernel<<<MM, blk>>>(x2, tmp, n3_g, n3_b, out, (float*)0);
}

// round 14
// speedup vs baseline: 1.1470x; 1.0648x over previous
#include <cuda_runtime.h>
#include <cuda_bf16.h>
#include <cstdint>
#include <math.h>

// Problem constants
#define BB   4
#define SS   1024
#define DD   1024
#define HH   16
#define DKK  64
#define DFFN 4096
#define MM   (BB*SS)        // 4096 token rows
#define BH   (BB*HH)        // 64
#define MI   (1024*1024)

// ---------------------------------------------------------------------------
// Scratch
// ---------------------------------------------------------------------------
__device__ float g_q[MM*DD];
__device__ float g_k[MM*DD];
__device__ float g_v[MM*DD];      // V TRANSPOSED: [(b*1024+col)*1024 + t]
__device__ float g_k2[MM*DD];     // CA k
__device__ float g_v2[MM*DD];     // CA v (transposed)
__device__ float g_attn[MM*DD];
__device__ float g_tmp[MM*DD];
__device__ float g_x1[MM*DD];
__device__ float g_x1r[MM*DD];    // tf32-rounded copy of x1
__device__ float g_x2[MM*DD];
__device__ float g_x2r[MM*DD];    // tf32-rounded copy of x2
__device__ float g_hidden[(long long)MM*DFFN];    // 67MB
__device__ float g_round[24ll*MI];                // rounded inputs/weights, 96MB

// ---------------------------------------------------------------------------
// helpers
// ---------------------------------------------------------------------------
__device__ __forceinline__ unsigned int f2tf32(float f) {
    unsigned int r;
    asm("cvt.rna.tf32.f32 %0, %1;" : "=r"(r) : "f"(f));
    return r;
}

__device__ __forceinline__ void mma_tf32(float (&c)[4],
                                         const unsigned int (&a)[4],
                                         const unsigned int (&b)[2]) {
    asm volatile(
        "mma.sync.aligned.m16n8k8.row.col.f32.tf32.tf32.f32 "
        "{%0,%1,%2,%3}, {%4,%5,%6,%7}, {%8,%9}, {%0,%1,%2,%3};"
        : "+f"(c[0]), "+f"(c[1]), "+f"(c[2]), "+f"(c[3])
        : "r"(a[0]), "r"(a[1]), "r"(a[2]), "r"(a[3]),
          "r"(b[0]), "r"(b[1]));
}

__device__ __forceinline__ void ldsm_x4(unsigned int (&r)[4], unsigned int a) {
    asm volatile("ldmatrix.sync.aligned.m8n8.x4.shared.b16 {%0,%1,%2,%3}, [%4];"
        : "=r"(r[0]), "=r"(r[1]), "=r"(r[2]), "=r"(r[3]) : "r"(a));
}
__device__ __forceinline__ void ldsm_x2(unsigned int (&r)[2], unsigned int a) {
    asm volatile("ldmatrix.sync.aligned.m8n8.x2.shared.b16 {%0,%1}, [%2];"
        : "=r"(r[0]), "=r"(r[1]) : "r"(a));
}

__device__ __forceinline__ void cp16(unsigned int saddr, const float* g) {
    asm volatile("cp.async.cg.shared.global [%0], [%1], 16;\n" :: "r"(saddr), "l"(g));
}
__device__ __forceinline__ void cp_commit() {
    asm volatile("cp.async.commit_group;\n" ::);
}
__device__ __forceinline__ void cp_wait1() {
    asm volatile("cp.async.wait_group 1;\n" ::);
}
__device__ __forceinline__ void cp_wait0() {
    asm volatile("cp.async.wait_group 0;\n" ::);
}

// ---------------------------------------------------------------------------
// Batched tf32 rounding pass.
// ---------------------------------------------------------------------------
#define RN 10
struct RTab {
    const float* src[RN];
    float*       dst[RN];
    int          n4[RN];
};

__global__ void __launch_bounds__(256) round_all(RTab rt)
{
    int z = blockIdx.z;
    int i = blockIdx.x * 256 + threadIdx.x;
    if (i >= rt.n4[z]) return;
    float4 v = ((const float4*)rt.src[z])[i];
    v.x = __uint_as_float(f2tf32(v.x));
    v.y = __uint_as_float(f2tf32(v.y));
    v.z = __uint_as_float(f2tf32(v.z));
    v.w = __uint_as_float(f2tf32(v.w));
    ((float4*)rt.dst[z])[i] = v;
}

// Per-z operand table for the merged projection launch.
struct P5 {
    const float* A[5];
    const float* B[5];
    const float* bias[5];
    float*       C[5];
    int          trans[5];
};

// ---------------------------------------------------------------------------
// Core 128x128 tf32 GEMM body (TN), 3-stage cp.async, wait_group 1,
// LDSM fragment loads. Operands must be pre-rounded to the tf32 grid.
// ---------------------------------------------------------------------------
template<bool RELU, bool ROUND_OUT>
__device__ __forceinline__ void gemm_body_128(
    const float* __restrict__ A, const float* __restrict__ B,
    const float* __restrict__ bias, float* __restrict__ C,
    int lda, int ldb, int ldc, int K, int trans_out, float* smem)
{
    constexpr int BM = 128, BN = 128, WM = 64, WN = 32;
    constexpr int MT = WM / 16;       // 4
    constexpr int NT = WN / 8;        // 4
    constexpr int NWN = BN / WN;      // 4

    float* AsBase = smem;                    // 3 stages of BM*36
    float* BsBase = smem + 3 * BM * 36;      // 3 stages of BN*36

    const int row0 = blockIdx.y * BM;
    const int col0 = blockIdx.x * BN;
    const int t    = threadIdx.x;
    const int w    = t >> 5;
    const int lane = t & 31;
    const int wm   = w / NWN;
    const int wn   = w % NWN;
    const int gr   = lane >> 2;
    const int gc   = lane & 3;

    const int m0 = t >> 3;
    const int kq = t & 7;

    const float* gA = A + (long long)(row0 + m0) * lda + kq * 4;
    const float* gB = B + (long long)(col0 + m0) * ldb + kq * 4;

    unsigned int aBase = (unsigned int)__cvta_generic_to_shared(AsBase);
    unsigned int bBase = (unsigned int)__cvta_generic_to_shared(BsBase);
    constexpr unsigned int stageA = BM * 36 * 4;
    constexpr unsigned int stageB = BN * 36 * 4;

    // LDSM lane-dependent byte offsets (stage-invariant)
    const unsigned int aOff = ((wm * WM + (lane & 15)) * 36 + (lane >> 4) * 4) * 4;
    const unsigned int bOff = ((wn * WN + (lane & 7)) * 36 + ((lane >> 3) & 1) * 4) * 4;

    float acc[MT][NT][4];
    #pragma unroll
    for (int i = 0; i < MT; i++)
        #pragma unroll
        for (int j = 0; j < NT; j++)
            #pragma unroll
            for (int r = 0; r < 4; r++) acc[i][j][r] = 0.f;

    const int nk = K >> 5;   // 32 or 128: both == 2 (mod 3)

    // prologue: tile 0 -> stage 0 (G0), tile 1 -> stage 1 (G1)
    #pragma unroll
    for (int i = 0; i < BM / 32; i++)
        cp16(aBase + ((m0 + 32 * i) * 36 + kq * 4) * 4, gA + (long long)(32 * i) * lda);
    #pragma unroll
    for (int i = 0; i < BN / 32; i++)
        cp16(bBase + ((m0 + 32 * i) * 36 + kq * 4) * 4, gB + (long long)(32 * i) * ldb);
    cp_commit();
    #pragma unroll
    for (int i = 0; i < BM / 32; i++)
        cp16(aBase + stageA + ((m0 + 32 * i) * 36 + kq * 4) * 4, gA + 32 + (long long)(32 * i) * lda);
    #pragma unroll
    for (int i = 0; i < BN / 32; i++)
        cp16(bBase + stageB + ((m0 + 32 * i) * 36 + kq * 4) * 4, gB + 32 + (long long)(32 * i) * ldb);
    cp_commit();

#define PREFETCH_TILE(W)                                                          \
    {                                                                             \
        const float* gA2 = gA + (it + 2) * 32;                                    \
        const float* gB2 = gB + (it + 2) * 32;                                    \
        _Pragma("unroll")                                                         \
        for (int i = 0; i < BM / 32; i++)                                         \
            cp16(aBase + (W) * stageA + ((m0 + 32 * i) * 36 + kq * 4) * 4,        \
                 gA2 + (long long)(32 * i) * lda);                                \
        _Pragma("unroll")                                                         \
        for (int i = 0; i < BN / 32; i++)                                         \
            cp16(bBase + (W) * stageB + ((m0 + 32 * i) * 36 + kq * 4) * 4,        \
                 gB2 + (long long)(32 * i) * ldb);                                \
    }

#define COMPUTE_TILE(S)                                                           \
    {                                                                             \
        const unsigned int aS = aBase + (S) * stageA + aOff;                      \
        const unsigned int bS = bBase + (S) * stageB + bOff;                      \
        _Pragma("unroll")                                                         \
        for (int ks = 0; ks < 32; ks += 8) {                                      \
            unsigned int af[MT][4];                                               \
            unsigned int bf[NT][2];                                               \
            _Pragma("unroll")                                                     \
            for (int mt = 0; mt < MT; mt++)                                       \
                ldsm_x4(af[mt], aS + (mt * (16 * 36) + ks) * 4);                  \
            _Pragma("unroll")                                                     \
            for (int nt = 0; nt < NT; nt++)                                       \
                ldsm_x2(bf[nt], bS + (nt * (8 * 36) + ks) * 4);                   \
            _Pragma("unroll")                                                     \
            for (int mt = 0; mt < MT; mt++)                                       \
                _Pragma("unroll")                                                 \
                for (int nt = 0; nt < NT; nt++)                                   \
                    mma_tf32(acc[mt][nt], af[mt], bf[nt]);                        \
        }                                                                         \
    }

#define GEMM_STEP(S, W)                                                           \
    {                                                                             \
        cp_wait1();                                                               \
        __syncthreads();                                                          \
        if (it + 2 < nk) PREFETCH_TILE(W);                                        \
        cp_commit();                                                              \
        COMPUTE_TILE(S);                                                          \
        it++;                                                                     \
    }

    int it = 0;
    while (it + 3 <= nk) {
        GEMM_STEP(0, 2)
        GEMM_STEP(1, 0)
        GEMM_STEP(2, 1)
    }
    // nk % 3 == 2 for K=1024 and K=4096: remainder tiles at stages 0, 1
    GEMM_STEP(0, 2)
    GEMM_STEP(1, 0)

#undef GEMM_STEP
#undef COMPUTE_TILE
#undef PREFETCH_TILE

    // ---- Epilogue ----
    #pragma unroll
    for (int mt = 0; mt < MT; mt++) {
        #pragma unroll
        for (int nt = 0; nt < NT; nt++) {
            int row = row0 + wm * WM + mt * 16 + gr;
            int col = col0 + wn * WN + nt * 8 + gc * 2;
            float b0 = 0.f, b1 = 0.f;
            if (bias) { b0 = bias[col]; b1 = bias[col + 1]; }
            float v0 = acc[mt][nt][0] + b0;
            float v1 = acc[mt][nt][1] + b1;
            float v2 = acc[mt][nt][2] + b0;
            float v3 = acc[mt][nt][3] + b1;
            if (RELU) {
                v0 = fmaxf(v0, 0.f); v1 = fmaxf(v1, 0.f);
                v2 = fmaxf(v2, 0.f); v3 = fmaxf(v3, 0.f);
            }
            if (ROUND_OUT) {
                v0 = __uint_as_float(f2tf32(v0));
                v1 = __uint_as_float(f2tf32(v1));
                v2 = __uint_as_float(f2tf32(v2));
                v3 = __uint_as_float(f2tf32(v3));
            }
            if (trans_out) {
                int rb = row >> 10;
                int tt = row & 1023;
                long long a0 = ((long long)(rb * 1024 + col) << 10) + tt;
                C[a0]            = v0;
                C[a0 + 1024]     = v1;
                C[a0 + 8]        = v2;
                C[a0 + 1024 + 8] = v3;
            } else {
                *(float2*)(C + (long long)row * ldc + col)       = make_float2(v0, v1);
                *(float2*)(C + (long long)(row + 8) * ldc + col) = make_float2(v2, v3);
            }
        }
    }
}

// Generic single-GEMM wrapper.
template<bool RELU, bool ROUND_OUT, bool TRANS_OUT>
__global__ void __launch_bounds__(256, 2) gemm_tc(
    const float* __restrict__ A, int lda,
    const float* __restrict__ B, int ldb,
    const float* __restrict__ bias,
    float* __restrict__ C, int ldc, int K)
{
    extern __shared__ float smem[];
    gemm_body_128<RELU, ROUND_OUT>(A, B, bias, C, lda, ldb, ldc, K,
                                   TRANS_OUT ? 1 : 0, smem);
}

// Merged independent projections: z selects operands (SAq,SAk,SAv,CAk,CAv).
__global__ void __launch_bounds__(256, 2) gemm_qkv5(P5 p, int K)
{
    extern __shared__ float smem[];
    const int z = blockIdx.z;
    gemm_body_128<false, true>(p.A[z], p.B[z], p.bias[z], p.C[z],
                               DD, DD, DD, K, p.trans[z], smem);
}

// ---------------------------------------------------------------------------
// Flash attention: cp.async double-buffered K/V, LDSM fragment loads.
// ---------------------------------------------------------------------------
#define FQT 128
#define FKT 64
#define FSB 68

template<bool CAUSAL>
__global__ void __launch_bounds__(256, 2) flash_attn(
    const float* __restrict__ Q, const float* __restrict__ K,
    const float* __restrict__ VT, float* __restrict__ O)
{
    extern __shared__ float sm[];
    float* Kb = sm;                       // [2][FKT][FSB]
    float* Vb = sm + 2 * FKT * FSB;       // [2][64][FSB]
    float* Pb = sm + 4 * FKT * FSB;       // [FQT][FSB]

    const int qi = CAUSAL ? ((int)gridDim.x - 1 - (int)blockIdx.x) : (int)blockIdx.x;
    const int bh = blockIdx.y;
    const int b  = bh >> 4;
    const int h  = bh & 15;

    const int t    = threadIdx.x;
    const int w    = t >> 5;
    const int lane = t & 31;
    const int gr   = lane >> 2;
    const int gc   = lane & 3;
    const int wrow = w * 16;

    const long long rowbase = (long long)b * SS;
    const float* Qp = Q + (rowbase + qi * FQT) * DD + h * 64;
    const float* Kp = K + rowbase * DD + h * 64;
    const float* Vp = VT + (((long long)(b * 1024 + h * 64)) << 10);
    float* Op = O + (rowbase + qi * FQT) * DD + h * 64;

    unsigned int kbase = (unsigned int)__cvta_generic_to_shared(Kb);
    unsigned int vbase = (unsigned int)__cvta_generic_to_shared(Vb);
    unsigned int pbase = (unsigned int)__cvta_generic_to_shared(Pb);
    constexpr unsigned int stageK = FKT * FSB * 4;

    // LDSM lane offsets
    const unsigned int nOff = ((lane & 7) * FSB + ((lane >> 3) & 1) * 4) * 4;  // B-frag (K/V)
    const unsigned int pOff = ((wrow + (lane & 15)) * FSB + (lane >> 4) * 4) * 4; // A-frag (P)

    #pragma unroll
    for (int i = 0; i < 8; i++) {
        int l  = t + i * 256;
        int m  = l >> 4;
        int q4 = l & 15;
        float4 v = *(const float4*)(Qp + (long long)m * DD + q4 * 4);
        *(float4*)&Pb[m * FSB + q4 * 4] = v;
    }
    __syncthreads();

    unsigned int qf[8][4];
    #pragma unroll
    for (int ks = 0; ks < 8; ks++)
        ldsm_x4(qf[ks], pbase + pOff + ks * 8 * 4);
    __syncthreads();

    float o[8][4];
    #pragma unroll
    for (int i = 0; i < 8; i++)
        #pragma unroll
        for (int r = 0; r < 4; r++) o[i][r] = 0.f;
    float m0 = -1e30f, m1 = -1e30f, l0 = 0.f, l1 = 0.f;

    const int rg0 = qi * FQT + wrow + gr;
    const int rg1 = rg0 + 8;
    const int jmax = CAUSAL ? (2 * qi + 1) : (SS / FKT - 1);

    #pragma unroll
    for (int i = 0; i < 4; i++) {
        int l  = t + i * 256;
        int tk = l >> 4;
        int q4 = l & 15;
        cp16(kbase + (tk * FSB + q4 * 4) * 4, Kp + (long long)tk * DD + q4 * 4);
    }
    #pragma unroll
    for (int i = 0; i < 4; i++) {
        int l  = t + i * 256;
        int d  = l >> 4;
        int t4 = l & 15;
        cp16(vbase + (d * FSB + t4 * 4) * 4, Vp + (((long long)d) << 10) + t4 * 4);
    }
    cp_commit();

    for (int j = 0; j <= jmax; j++) {
        const int cur = j & 1;
        if (j < jmax) {
            const int nxt = cur ^ 1;
            #pragma unroll
            for (int i = 0; i < 4; i++) {
                int l  = t + i * 256;
                int tk = l >> 4;
                int q4 = l & 15;
                cp16(kbase + nxt * stageK + (tk * FSB + q4 * 4) * 4,
                     Kp + (long long)((j + 1) * FKT + tk) * DD + q4 * 4);
            }
            #pragma unroll
            for (int i = 0; i < 4; i++) {
                int l  = t + i * 256;
                int d  = l >> 4;
                int t4 = l & 15;
                cp16(vbase + nxt * stageK + (d * FSB + t4 * 4) * 4,
                     Vp + (((long long)d) << 10) + (j + 1) * FKT + t4 * 4);
            }
            cp_commit();
            cp_wait1();
        } else {
            cp_wait0();
        }
        __syncthreads();

        const unsigned int kS = kbase + cur * stageK + nOff;
        const unsigned int vS = vbase + cur * stageK + nOff;

        float s[8][4];
        #pragma unroll
        for (int i = 0; i < 8; i++)
            #pragma unroll
            for (int r = 0; r < 4; r++) s[i][r] = 0.f;

        #pragma unroll
        for (int ks = 0; ks < 8; ks++) {
            #pragma unroll
            for (int nt = 0; nt < 8; nt++) {
                unsigned int bf[2];
                ldsm_x2(bf, kS + (nt * 8 * FSB + ks * 8) * 4);
                mma_tf32(s[nt], qf[ks], bf);
            }
        }

        float tm0 = -1e30f, tm1 = -1e30f;
        #pragma unroll
        for (int nt = 0; nt < 8; nt++) {
            s[nt][0] *= 0.125f; s[nt][1] *= 0.125f;
            s[nt][2] *= 0.125f; s[nt][3] *= 0.125f;
            if (CAUSAL && j >= 2 * qi) {
                int c0 = j * FKT + nt * 8 + 2 * gc;
                int c1 = c0 + 1;
                if (c0 > rg0) s[nt][0] = -1e30f;
                if (c1 > rg0) s[nt][1] = -1e30f;
                if (c0 > rg1) s[nt][2] = -1e30f;
                if (c1 > rg1) s[nt][3] = -1e30f;
            }
            tm0 = fmaxf(tm0, fmaxf(s[nt][0], s[nt][1]));
            tm1 = fmaxf(tm1, fmaxf(s[nt][2], s[nt][3]));
        }
        tm0 = fmaxf(tm0, __shfl_xor_sync(0xffffffffu, tm0, 1));
        tm0 = fmaxf(tm0, __shfl_xor_sync(0xffffffffu, tm0, 2));
        tm1 = fmaxf(tm1, __shfl_xor_sync(0xffffffffu, tm1, 1));
        tm1 = fmaxf(tm1, __shfl_xor_sync(0xffffffffu, tm1, 2));

        float mn0 = fmaxf(m0, tm0);
        float mn1 = fmaxf(m1, tm1);
        float sc0 = __expf(m0 - mn0);
        float sc1 = __expf(m1 - mn1);
        float ps0 = 0.f, ps1 = 0.f;

        #pragma unroll
        for (int nt = 0; nt < 8; nt++) {
            float p00 = __expf(s[nt][0] - mn0);
            float p01 = __expf(s[nt][1] - mn0);
            float p10 = __expf(s[nt][2] - mn1);
            float p11 = __expf(s[nt][3] - mn1);
            ps0 += p00 + p01;
            ps1 += p10 + p11;
            *(float2*)&Pb[(wrow + gr    ) * FSB + nt * 8 + 2 * gc] = make_float2(p00, p01);
            *(float2*)&Pb[(wrow + gr + 8) * FSB + nt * 8 + 2 * gc] = make_float2(p10, p11);
        }
        ps0 += __shfl_xor_sync(0xffffffffu, ps0, 1);
        ps0 += __shfl_xor_sync(0xffffffffu, ps0, 2);
        ps1 += __shfl_xor_sync(0xffffffffu, ps1, 1);
        ps1 += __shfl_xor_sync(0xffffffffu, ps1, 2);

        l0 = l0 * sc0 + ps0;
        l1 = l1 * sc1 + ps1;
        m0 = mn0; m1 = mn1;

        #pragma unroll
        for (int nt = 0; nt < 8; nt++) {
            o[nt][0] *= sc0; o[nt][1] *= sc0;
            o[nt][2] *= sc1; o[nt][3] *= sc1;
        }
        __syncwarp();

        #pragma unroll
        for (int ks = 0; ks < 8; ks++) {
            unsigned int pf[4];
            ldsm_x4(pf, pbase + pOff + ks * 8 * 4);
            #pragma unroll
            for (int nt = 0; nt < 8; nt++) {
                unsigned int bf[2];
                ldsm_x2(bf, vS + (nt * 8 * FSB + ks * 8) * 4);
                mma_tf32(o[nt], pf, bf);
            }
        }
        __syncthreads();
    }

    float inv0 = 1.f / l0;
    float inv1 = 1.f / l1;
    #pragma unroll
    for (int nt = 0; nt < 8; nt++) {
        int c = nt * 8 + 2 * gc;
        *(float2*)(Op + (long long)(wrow + gr    ) * DD + c) =
            make_float2(__uint_as_float(f2tf32(o[nt][0] * inv0)),
                        __uint_as_float(f2tf32(o[nt][1] * inv0)));
        *(float2*)(Op + (long long)(wrow + gr + 8) * DD + c) =
            make_float2(__uint_as_float(f2tf32(o[nt][2] * inv1)),
                        __uint_as_float(f2tf32(o[nt][3] * inv1)));
    }
}

// ---------------------------------------------------------------------------
// out = LayerNorm(a + b) * g + beta ; optional tf32-rounded second output.
// ---------------------------------------------------------------------------
__global__ void __launch_bounds__(256) add_ln_kernel(
    const float* __restrict__ A, const float* __restrict__ Bv,
    const float* __restrict__ g, const float* __restrict__ be,
    float* __restrict__ out, float* __restrict__ out_r)
{
    __shared__ float redS[8];
    __shared__ float redQ[8];
    long long row = blockIdx.x;
    int t = threadIdx.x;

    float4 a = *(const float4*)(A  + row * DD + t * 4);
    float4 b = *(const float4*)(Bv + row * DD + t * 4);
    float4 s;
    s.x = a.x + b.x; s.y = a.y + b.y; s.z = a.z + b.z; s.w = a.w + b.w;

    float sum = s.x + s.y + s.z + s.w;
    float sq  = s.x*s.x + s.y*s.y + s.z*s.z + s.w*s.w;
    #pragma unroll
    for (int o = 16; o > 0; o >>= 1) {
        sum += __shfl_xor_sync(0xffffffffu, sum, o);
        sq  += __shfl_xor_sync(0xffffffffu, sq,  o);
    }
    if ((t & 31) == 0) { redS[t >> 5] = sum; redQ[t >> 5] = sq; }
    __syncthreads();
    sum = 0.f; sq = 0.f;
    #pragma unroll
    for (int i = 0; i < 8; i++) { sum += redS[i]; sq += redQ[i]; }

    float mean = sum * (1.0f / DD);
    float var  = sq  * (1.0f / DD) - mean * mean;
    float rstd = rsqrtf(var + 1e-5f);

    float4 gg = *(const float4*)(g  + t * 4);
    float4 bb = *(const float4*)(be + t * 4);
    float4 o;
    o.x = (s.x - mean) * rstd * gg.x + bb.x;
    o.y = (s.y - mean) * rstd * gg.y + bb.y;
    o.z = (s.z - mean) * rstd * gg.z + bb.z;
    o.w = (s.w - mean) * rstd * gg.w + bb.w;
    *(float4*)(out + row * DD + t * 4) = o;
    if (out_r) {
        float4 r;
        r.x = __uint_as_float(f2tf32(o.x));
        r.y = __uint_as_float(f2tf32(o.y));
        r.z = __uint_as_float(f2tf32(o.z));
        r.w = __uint_as_float(f2tf32(o.w));
        *(float4*)(out_r + row * DD + t * 4) = r;
    }
}

// ---------------------------------------------------------------------------
// Launch
// ---------------------------------------------------------------------------
extern "C" void kernel_launch(void* const* d_in, const int* in_sizes, int n_in,
                              void* d_out, int out_size)
{
    const float* x        = (const float*)d_in[0];
    const float* enc      = (const float*)d_in[1];
    const float* sa_wq    = (const float*)d_in[4];
    const float* sa_bq    = (const float*)d_in[5];
    const float* sa_wk    = (const float*)d_in[6];
    const float* sa_bk    = (const float*)d_in[7];
    const float* sa_wv    = (const float*)d_in[8];
    const float* sa_bv    = (const float*)d_in[9];
    const float* sa_wo    = (const float*)d_in[10];
    const float* sa_bo    = (const float*)d_in[11];
    const float* ca_in_w  = (const float*)d_in[12];
    const float* ca_in_b  = (const float*)d_in[13];
    const float* ca_out_w = (const float*)d_in[14];
    const float* ca_out_b = (const float*)d_in[15];
    const float* ff_w1    = (const float*)d_in[16];
    const float* ff_b1    = (const float*)d_in[17];
    const float* ff_w2    = (const float*)d_in[18];
    const float* ff_b2    = (const float*)d_in[19];
    const float* n1_g     = (const float*)d_in[20];
    const float* n1_b     = (const float*)d_in[21];
    const float* n2_g     = (const float*)d_in[22];
    const float* n2_b     = (const float*)d_in[23];
    const float* n3_g     = (const float*)d_in[24];
    const float* n3_b     = (const float*)d_in[25];
    float* out = (float*)d_out;

    float *q, *k, *v, *k2, *v2, *attn, *tmp, *x1, *x1r, *x2, *x2r, *hid, *rb;
    cudaGetSymbolAddress((void**)&q,    g_q);
    cudaGetSymbolAddress((void**)&k,    g_k);
    cudaGetSymbolAddress((void**)&v,    g_v);
    cudaGetSymbolAddress((void**)&k2,   g_k2);
    cudaGetSymbolAddress((void**)&v2,   g_v2);
    cudaGetSymbolAddress((void**)&attn, g_attn);
    cudaGetSymbolAddress((void**)&tmp,  g_tmp);
    cudaGetSymbolAddress((void**)&x1,   g_x1);
    cudaGetSymbolAddress((void**)&x1r,  g_x1r);
    cudaGetSymbolAddress((void**)&x2,   g_x2);
    cudaGetSymbolAddress((void**)&x2r,  g_x2r);
    cudaGetSymbolAddress((void**)&hid,  g_hidden);
    cudaGetSymbolAddress((void**)&rb,   g_round);

    float* x_r    = rb;
    float* enc_r  = rb + 4ll*MI;
    float* wq_r   = rb + 8ll*MI;
    float* wk_r   = rb + 9ll*MI;
    float* wv_r   = rb + 10ll*MI;
    float* wo_r   = rb + 11ll*MI;
    float* caw_r  = rb + 12ll*MI;   // 3M floats
    float* cao_r  = rb + 15ll*MI;
    float* ffw1_r = rb + 16ll*MI;
    float* ffw2_r = rb + 20ll*MI;

    const int SMEM_TC = 3 * (128 + 128) * 36 * 4;       // 110592 bytes
    const int SMEM_FL = (4 * FKT + FQT) * FSB * 4;      // 104448 bytes
    cudaFuncSetAttribute(gemm_tc<false,false,false>,
                         cudaFuncAttributeMaxDynamicSharedMemorySize, SMEM_TC);
    cudaFuncSetAttribute(gemm_tc<true,true,false>,
                         cudaFuncAttributeMaxDynamicSharedMemorySize, SMEM_TC);
    cudaFuncSetAttribute(gemm_tc<false,true,false>,
                         cudaFuncAttributeMaxDynamicSharedMemorySize, SMEM_TC);
    cudaFuncSetAttribute(gemm_qkv5,
                         cudaFuncAttributeMaxDynamicSharedMemorySize, SMEM_TC);
    cudaFuncSetAttribute(flash_attn<true>,
                         cudaFuncAttributeMaxDynamicSharedMemorySize, SMEM_FL);
    cudaFuncSetAttribute(flash_attn<false>,
                         cudaFuncAttributeMaxDynamicSharedMemorySize, SMEM_FL);

    dim3 blk(256);
    dim3 gProj(DD/128, MM/128, 1);
    dim3 gQKV5(DD/128, MM/128, 5);
    dim3 gFF1(DFFN/128, MM/128, 1);
    dim3 gFlash(SS/128, BH, 1);

    // ---- Pre-round all read-only GEMM operands ----
    RTab rt;
    rt.src[0] = x;        rt.dst[0] = x_r;    rt.n4[0] = 4*MI/4;
    rt.src[1] = enc;      rt.dst[1] = enc_r;  rt.n4[1] = 4*MI/4;
    rt.src[2] = sa_wq;    rt.dst[2] = wq_r;   rt.n4[2] = MI/4;
    rt.src[3] = sa_wk;    rt.dst[3] = wk_r;   rt.n4[3] = MI/4;
    rt.src[4] = sa_wv;    rt.dst[4] = wv_r;   rt.n4[4] = MI/4;
    rt.src[5] = sa_wo;    rt.dst[5] = wo_r;   rt.n4[5] = MI/4;
    rt.src[6] = ca_in_w;  rt.dst[6] = caw_r;  rt.n4[6] = 3*MI/4;
    rt.src[7] = ca_out_w; rt.dst[7] = cao_r;  rt.n4[7] = MI/4;
    rt.src[8] = ff_w1;    rt.dst[8] = ffw1_r; rt.n4[8] = 4*MI/4;
    rt.src[9] = ff_w2;    rt.dst[9] = ffw2_r; rt.n4[9] = 4*MI/4;
    round_all<<<dim3(4096, 1, RN), blk>>>(rt);

    // ---- Merged independent projections (SA q,k,v + CA k,v) ----
    P5 p;
    p.A[0] = x_r;   p.B[0] = wq_r;            p.bias[0] = sa_bq;          p.C[0] = q;  p.trans[0] = 0;
    p.A[1] = x_r;   p.B[1] = wk_r;            p.bias[1] = sa_bk;          p.C[1] = k;  p.trans[1] = 0;
    p.A[2] = x_r;   p.B[2] = wv_r;            p.bias[2] = sa_bv;          p.C[2] = v;  p.trans[2] = 1;
    p.A[3] = enc_r; p.B[3] = caw_r + (long long)DD*DD; p.bias[3] = ca_in_b + DD;   p.C[3] = k2; p.trans[3] = 0;
    p.A[4] = enc_r; p.B[4] = caw_r + 2ll*DD*DD;        p.bias[4] = ca_in_b + 2*DD; p.C[4] = v2; p.trans[4] = 1;
    gemm_qkv5<<<gQKV5, blk, SMEM_TC>>>(p, DD);

    // ---- Self-attention ----
    flash_attn<true><<<gFlash, blk, SMEM_FL>>>(q, k, v, attn);
    gemm_tc<false,false,false><<<gProj, blk, SMEM_TC>>>(attn, DD, wo_r, DD, sa_bo, tmp, DD, DD);
    add_ln_kernel<<<MM, blk>>>(x, tmp, n1_g, n1_b, x1, x1r);

    // ---- Cross-attention ----
    gemm_tc<false,true,false><<<gProj, blk, SMEM_TC>>>(x1r, DD, caw_r, DD, ca_in_b, q, DD, DD);
    flash_attn<false><<<gFlash, blk, SMEM_FL>>>(q, k2, v2, attn);
    gemm_tc<false,false,false><<<gProj, blk, SMEM_TC>>>(attn, DD, cao_r, DD, ca_out_b, tmp, DD, DD);
    add_ln_kernel<<<MM, blk>>>(x1, tmp, n2_g, n2_b, x2, x2r);

    // ---- FFN ----
    gemm_tc<true,true,false  ><<<gFF1,  blk, SMEM_TC>>>(x2r, DD,   ffw1_r, DD,   ff_b1, hid, DFFN, DD);
    gemm_tc<false,false,false><<<gProj, blk, SMEM_TC>>>(hid, DFFN, ffw2_r, DFFN, ff_b2, tmp, DD,   DFFN);
    add_ln_kernel<<<MM, blk>>>(x2, tmp, n3_g, n3_b, out, (float*)0);
}